// round 2
// baseline (speedup 1.0000x reference)
#include <cuda_runtime.h>
#include <stdint.h>

// out[b,i,j,:] = pe[clamp(128 + j - i, 0, 256), :]
// B=4, S=512, D=128, fp32. Pure store-bandwidth-bound (512 MiB written).
//
// Key structure: rel depends only on d = j - i, so all rows along a diagonal
// copy the SAME 512B pe row. One warp handles a 16-row chunk of one diagonal:
// it loads its pe float4 ONCE into a register, then streams 16 STG.128s.
// This removes all redundant LDG traffic from L1 and gives each warp 16
// independent stores in flight.

__global__ __launch_bounds__(256) void relpos_diag(
    const float4* __restrict__ pe,   // [512][32] float4
    float4* __restrict__ out)        // [B][512][512][32] float4
{
    const int S = 512;
    const int lane = threadIdx.x & 31;
    const int warp = threadIdx.x >> 5;            // 0..7
    const int chunk = blockIdx.x * 8 + warp;      // 0..31 (16 i's each)
    const int i0 = chunk << 4;
    const int dd = (int)blockIdx.y - (S - 1);     // diagonal: -511..511
    const int b  = blockIdx.z;

    int rel = 128 + dd;
    rel = rel < 0 ? 0 : (rel > 256 ? 256 : rel);

    // valid i range on this diagonal: i in [max(0,-dd), min(S, S-dd))
    const int lo = dd < 0 ? -dd : 0;
    const int hi = dd > 0 ? S - dd : S;
    int ibeg = i0 > lo ? i0 : lo;
    int iend = (i0 + 16) < hi ? (i0 + 16) : hi;
    if (ibeg >= iend) return;

    // one 512B row read per warp, L1/L2-resident table
    const float4 v = pe[rel * 32 + lane];

    // float4 index of (b, ibeg, ibeg+dd, lane*4)
    size_t off = ((size_t)(b * S + ibeg) * S + (size_t)(ibeg + dd)) * 32 + lane;
    const size_t stride = (size_t)(S + 1) * 32;   // (i,j) -> (i+1,j+1)

    #pragma unroll 4
    for (int i = ibeg; i < iend; ++i) {
        __stcs(out + off, v);   // streaming store: write-once, evict-first
        off += stride;
    }
}

extern "C" void kernel_launch(void* const* d_in, const int* in_sizes, int n_in,
                              void* d_out, int out_size)
{
    // d_in[0] = x (int32 [B,512], shape-only), d_in[1] = pe (float32 [512,128])
    const float4* pe = (const float4*)d_in[1];
    float4* out = (float4*)d_out;

    const int S = 512;
    const int B = out_size / (S * S * 128);       // = 4

    dim3 grid(4, 2 * S - 1, B);                   // (i-chunks, diagonals, batch)
    relpos_diag<<<grid, 256>>>(pe, out);
}

// round 3
// speedup vs baseline: 1.0214x; 1.0214x over previous
#include <cuda_runtime.h>
#include <stdint.h>

// out[b,i,j,:] = pe[clamp(128 + j - i, 0, 256), :]
// B=4, S=512, D=128 fp32. Pure HBM-write-bound (512 MiB stores).
//
// Batch-fold: out[b] is identical for all b, so each warp loads its pe
// float4s ONCE and stores them to all B batch images. Warp = (i, 4
// consecutive j's): 4 L1-resident LDG.128 + 16 independent, fully
// contiguous STG.128. Consecutive warps write consecutive 2KB chunks in
// each batch stream -> maximal DRAM page locality (the pattern that
// measured fastest in round 1).

__global__ __launch_bounds__(256) void relpos_bfold(
    const float4* __restrict__ pe,   // [512][32] float4
    float4* __restrict__ out,        // [B][512][512][32] float4
    int B)
{
    const int S = 512;
    const int lane = threadIdx.x & 31;
    const int warp = threadIdx.x >> 5;        // 0..7
    const int i  = blockIdx.y;                // 0..511
    const int j0 = (blockIdx.x * 8 + warp) << 2;  // 0,4,...,508

    // gather 4 pe rows (table is L1-resident after warm-up)
    float4 v[4];
    #pragma unroll
    for (int t = 0; t < 4; ++t) {
        int rel = 128 + (j0 + t) - i;
        rel = rel < 0 ? 0 : (rel > 256 ? 256 : rel);
        v[t] = pe[rel * 32 + lane];
    }

    // 16 independent contiguous stores: 4 j's x B batches
    size_t base = ((size_t)i * S + j0) * 32 + lane;
    const size_t bstride = (size_t)S * S * 32;    // one batch image, in float4s

    #pragma unroll 4
    for (int b = 0; b < B; ++b) {
        #pragma unroll
        for (int t = 0; t < 4; ++t)
            out[base + t * 32] = v[t];
        base += bstride;
    }
}

extern "C" void kernel_launch(void* const* d_in, const int* in_sizes, int n_in,
                              void* d_out, int out_size)
{
    // d_in[0] = x (int32 [B,512], shape-only), d_in[1] = pe (float32 [512,128])
    const float4* pe = (const float4*)d_in[1];
    float4* out = (float4*)d_out;

    const int S = 512;
    const int B = out_size / (S * S * 128);   // = 4

    // x: 16 blocks x 8 warps x 4 j's = 512 j's ; y: i
    dim3 grid(16, S, 1);
    relpos_bfold<<<grid, 256>>>(pe, out, B);
}